// round 5
// baseline (speedup 1.0000x reference)
#include <cuda_runtime.h>
#include <cstdint>

#define D_MODEL_C 1024
#define DK_C 64
#define B_C 4
#define S_C 4096
#define NROWS_C (B_C * S_C)
#define NSPLIT 4
#define KV_PER_SPLIT (S_C / NSPLIT)          // 1024
#define TILES_PER_SPLIT (KV_PER_SPLIT / 64)  // 16

// Scratch (fp32). Static device arrays: allocation-free.
__device__ float g_Q[NROWS_C * DK_C];
__device__ float g_K[NROWS_C * DK_C];
__device__ float g_V[NROWS_C * DK_C];
__device__ float g_Opart[NSPLIT * NROWS_C * DK_C];   // unnormalized partial O
__device__ float g_m[NSPLIT * NROWS_C];
__device__ float g_l[NSPLIT * NROWS_C];

static __device__ __forceinline__ uint32_t f2tf32(float f) {
    uint32_t u;
    asm("cvt.rna.tf32.f32 %0, %1;" : "=r"(u) : "f"(f));
    return u;
}
static __device__ __forceinline__ float exp2_approx(float x) {
    float y;
    asm("ex2.approx.f32 %0, %1;" : "=f"(y) : "f"(x));
    return y;
}
static __device__ __forceinline__ void mma_tf32(float c[4], const uint32_t a[4], const uint32_t b[2]) {
    asm volatile(
        "mma.sync.aligned.m16n8k8.row.col.f32.tf32.tf32.f32 "
        "{%0,%1,%2,%3}, {%4,%5,%6,%7}, {%8,%9}, {%0,%1,%2,%3};\n"
        : "+f"(c[0]), "+f"(c[1]), "+f"(c[2]), "+f"(c[3])
        : "r"(a[0]), "r"(a[1]), "r"(a[2]), "r"(a[3]), "r"(b[0]), "r"(b[1]));
}

// ---------------------------------------------------------------------------
// Kernel 1: QKV projection, 3xTF32 split precision, hi/lo interleaved float2.
// Grid (row_tiles, 3 matrices). 256 threads (8 warps): warp = row-slab x col-half.
// Each warp: 16 rows x 32 cols of ONE matrix.
// ---------------------------------------------------------------------------
#define PKC 16
#define ES2_S 20   // emb pair stride (float2 units), ≡4 mod 16 -> conflict-free LDS.64
#define WS2_S 68   // W pair stride (float2 units),  ≡4 mod 16 -> conflict-free LDS.64

__global__ __launch_bounds__(256)
void qkv_proj_kernel(const float* __restrict__ emb,
                     const float* __restrict__ Wq, const float* __restrict__ bq,
                     const float* __restrict__ Wk, const float* __restrict__ bk,
                     const float* __restrict__ Wv, const float* __restrict__ bv)
{
    __shared__ float2 Es[64 * ES2_S];    // emb tile 64x16 as {hi,lo}
    __shared__ float2 Wp[PKC * WS2_S];   // W tile 16x64 as {hi,lo}

    const int tid  = threadIdx.x;
    const int warp = tid >> 5;
    const int lane = tid & 31;
    const int rs   = warp & 3;      // row slab
    const int ch   = warp >> 2;     // col half
    const int row0 = blockIdx.x * 64;
    const int mat  = blockIdx.y;

    const float* W    = (mat == 0) ? Wq : (mat == 1) ? Wk : Wv;
    const float* bias = (mat == 0) ? bq : (mat == 1) ? bk : bv;
    float* outp       = (mat == 0) ? g_Q : (mat == 1) ? g_K : g_V;

    float acc[4][4];
#pragma unroll
    for (int n = 0; n < 4; ++n)
#pragma unroll
        for (int j = 0; j < 4; ++j) acc[n][j] = 0.f;

    const int ar = rs * 16 + (lane >> 2);
    const int ac = lane & 3;
    const int g  = lane >> 2;

    // writer indices (constant across kc)
    const int er  = tid >> 2;            // emb row 0..63
    const int ec4 = (tid & 3) * 4;       // emb col 0,4,8,12
    const int wr  = tid >> 4;            // W row 0..15
    const int wc4 = (tid & 15) * 4;      // W col 0..60

    for (int kc = 0; kc < D_MODEL_C / PKC; ++kc) {
        __syncthreads();
        // emb tile 64x16: one float4 per thread -> two float4 smem stores
        {
            float4 v = *reinterpret_cast<const float4*>(
                &emb[(size_t)(row0 + er) * D_MODEL_C + kc * PKC + ec4]);
            float hx = __uint_as_float(f2tf32(v.x));
            float hy = __uint_as_float(f2tf32(v.y));
            float hz = __uint_as_float(f2tf32(v.z));
            float hw = __uint_as_float(f2tf32(v.w));
            float4 p0 = make_float4(hx, __uint_as_float(f2tf32(v.x - hx)),
                                    hy, __uint_as_float(f2tf32(v.y - hy)));
            float4 p1 = make_float4(hz, __uint_as_float(f2tf32(v.z - hz)),
                                    hw, __uint_as_float(f2tf32(v.w - hw)));
            *reinterpret_cast<float4*>(&Es[er * ES2_S + ec4])     = p0;
            *reinterpret_cast<float4*>(&Es[er * ES2_S + ec4 + 2]) = p1;
        }
        // W tile 16x64: one float4 per thread -> two float4 smem stores
        {
            float4 v = *reinterpret_cast<const float4*>(
                &W[(size_t)(kc * PKC + wr) * DK_C + wc4]);
            float hx = __uint_as_float(f2tf32(v.x));
            float hy = __uint_as_float(f2tf32(v.y));
            float hz = __uint_as_float(f2tf32(v.z));
            float hw = __uint_as_float(f2tf32(v.w));
            float4 p0 = make_float4(hx, __uint_as_float(f2tf32(v.x - hx)),
                                    hy, __uint_as_float(f2tf32(v.y - hy)));
            float4 p1 = make_float4(hz, __uint_as_float(f2tf32(v.z - hz)),
                                    hw, __uint_as_float(f2tf32(v.w - hw)));
            *reinterpret_cast<float4*>(&Wp[wr * WS2_S + wc4])     = p0;
            *reinterpret_cast<float4*>(&Wp[wr * WS2_S + wc4 + 2]) = p1;
        }
        __syncthreads();
#pragma unroll
        for (int ks = 0; ks < PKC / 8; ++ks) {
            float2 a0 = Es[ar * ES2_S + ks * 8 + ac];
            float2 a1 = Es[(ar + 8) * ES2_S + ks * 8 + ac];
            float2 a2 = Es[ar * ES2_S + ks * 8 + ac + 4];
            float2 a3 = Es[(ar + 8) * ES2_S + ks * 8 + ac + 4];
            uint32_t ah[4] = {__float_as_uint(a0.x), __float_as_uint(a1.x),
                              __float_as_uint(a2.x), __float_as_uint(a3.x)};
            uint32_t al[4] = {__float_as_uint(a0.y), __float_as_uint(a1.y),
                              __float_as_uint(a2.y), __float_as_uint(a3.y)};
            const int brow = ks * 8 + ac;
#pragma unroll
            for (int n = 0; n < 4; ++n) {
                const int bcol = ch * 32 + n * 8 + g;
                float2 b0 = Wp[brow * WS2_S + bcol];
                float2 b1 = Wp[(brow + 4) * WS2_S + bcol];
                uint32_t bh[2] = {__float_as_uint(b0.x), __float_as_uint(b1.x)};
                uint32_t bl[2] = {__float_as_uint(b0.y), __float_as_uint(b1.y)};
                // 3xTF32: hi*hi + hi*lo + lo*hi (lo*lo dropped)
                mma_tf32(acc[n], ah, bh);
                mma_tf32(acc[n], ah, bl);
                mma_tf32(acc[n], al, bh);
            }
        }
    }
    const int r  = row0 + ar;
    const int cb = ac * 2;
#pragma unroll
    for (int n = 0; n < 4; ++n) {
        int col = ch * 32 + n * 8 + cb;
        float b0 = bias[col], b1 = bias[col + 1];
        *reinterpret_cast<float2*>(&outp[(size_t)r * DK_C + col]) =
            make_float2(acc[n][0] + b0, acc[n][1] + b1);
        *reinterpret_cast<float2*>(&outp[(size_t)(r + 8) * DK_C + col]) =
            make_float2(acc[n][2] + b0, acc[n][3] + b1);
    }
}

// ---------------------------------------------------------------------------
// Kernel 2: flash attention, split-KV (4 splits). Br=Bc=64, 4 warps.
// (unchanged from round 3 — it passed and improved)
// ---------------------------------------------------------------------------
#define KPS 68
#define VSS 72

__global__ __launch_bounds__(128)
void attn_kernel()
{
    __shared__ float KP[64 * KPS];   // Q staging, then K tile, then P tile
    __shared__ float Vs[64 * VSS];   // V tile

    const int tid   = threadIdx.x;
    const int warp  = tid >> 5;
    const int lane  = tid & 31;
    const int b     = blockIdx.y;
    const int q0    = blockIdx.x * 64;
    const int split = blockIdx.z;
    const int t0    = split * TILES_PER_SPLIT;

    const float* Qg = g_Q + ((size_t)b * S_C + q0) * DK_C;
    const float* Kg = g_K + (size_t)b * S_C * DK_C;
    const float* Vg = g_V + (size_t)b * S_C * DK_C;

#pragma unroll
    for (int i = 0; i < 8; ++i) {
        int id = tid + i * 128;
        int r = id >> 4, c4 = (id & 15) * 4;
        *reinterpret_cast<float4*>(&KP[r * KPS + c4]) =
            *reinterpret_cast<const float4*>(&Qg[(size_t)r * DK_C + c4]);
    }
    __syncthreads();

    const int ar = warp * 16 + (lane >> 2);
    const int ac = lane & 31 & 3;
    const int g  = lane >> 2;
    const float qsc = 1.4426950408889634f * 0.125f;  // log2(e)/sqrt(dk)
    uint32_t qf[8][4];
#pragma unroll
    for (int ks = 0; ks < 8; ++ks) {
        qf[ks][0] = f2tf32(KP[ar * KPS + ks * 8 + ac] * qsc);
        qf[ks][1] = f2tf32(KP[(ar + 8) * KPS + ks * 8 + ac] * qsc);
        qf[ks][2] = f2tf32(KP[ar * KPS + ks * 8 + ac + 4] * qsc);
        qf[ks][3] = f2tf32(KP[(ar + 8) * KPS + ks * 8 + ac + 4] * qsc);
    }

    float o[8][4];
#pragma unroll
    for (int n = 0; n < 8; ++n)
#pragma unroll
        for (int j = 0; j < 4; ++j) o[n][j] = 0.f;
    float m0 = -1e30f, m1 = -1e30f, l0 = 0.f, l1 = 0.f;

    for (int tt = 0; tt < TILES_PER_SPLIT; ++tt) {
        const int t = t0 + tt;
        __syncthreads();
        const float* Kt = Kg + (size_t)t * 64 * DK_C;
        const float* Vt = Vg + (size_t)t * 64 * DK_C;
#pragma unroll
        for (int i = 0; i < 8; ++i) {
            int id = tid + i * 128;
            int r = id >> 4, c4 = (id & 15) * 4;
            float4 kv = *reinterpret_cast<const float4*>(&Kt[(size_t)r * DK_C + c4]);
            float4 vv = *reinterpret_cast<const float4*>(&Vt[(size_t)r * DK_C + c4]);
            float* kd = &KP[r * KPS + c4];
            float* vd = &Vs[r * VSS + c4];
            kd[0] = __uint_as_float(f2tf32(kv.x));
            kd[1] = __uint_as_float(f2tf32(kv.y));
            kd[2] = __uint_as_float(f2tf32(kv.z));
            kd[3] = __uint_as_float(f2tf32(kv.w));
            vd[0] = __uint_as_float(f2tf32(vv.x));
            vd[1] = __uint_as_float(f2tf32(vv.y));
            vd[2] = __uint_as_float(f2tf32(vv.z));
            vd[3] = __uint_as_float(f2tf32(vv.w));
        }
        __syncthreads();

        float s[8][4];
#pragma unroll
        for (int n = 0; n < 8; ++n)
#pragma unroll
            for (int j = 0; j < 4; ++j) s[n][j] = 0.f;
#pragma unroll
        for (int ks = 0; ks < 8; ++ks) {
#pragma unroll
            for (int n = 0; n < 8; ++n) {
                uint32_t bf[2];
                bf[0] = __float_as_uint(KP[(n * 8 + g) * KPS + ks * 8 + ac]);
                bf[1] = __float_as_uint(KP[(n * 8 + g) * KPS + ks * 8 + ac + 4]);
                mma_tf32(s[n], qf[ks], bf);
            }
        }

        float mx0 = m0, mx1 = m1;
#pragma unroll
        for (int n = 0; n < 8; ++n) {
            mx0 = fmaxf(mx0, fmaxf(s[n][0], s[n][1]));
            mx1 = fmaxf(mx1, fmaxf(s[n][2], s[n][3]));
        }
        mx0 = fmaxf(mx0, __shfl_xor_sync(0xffffffffu, mx0, 1));
        mx0 = fmaxf(mx0, __shfl_xor_sync(0xffffffffu, mx0, 2));
        mx1 = fmaxf(mx1, __shfl_xor_sync(0xffffffffu, mx1, 1));
        mx1 = fmaxf(mx1, __shfl_xor_sync(0xffffffffu, mx1, 2));
        float a0 = exp2_approx(m0 - mx0);
        float a1 = exp2_approx(m1 - mx1);
        float rs0 = 0.f, rs1 = 0.f;
#pragma unroll
        for (int n = 0; n < 8; ++n) {
            s[n][0] = exp2_approx(s[n][0] - mx0);
            s[n][1] = exp2_approx(s[n][1] - mx0);
            s[n][2] = exp2_approx(s[n][2] - mx1);
            s[n][3] = exp2_approx(s[n][3] - mx1);
            rs0 += s[n][0] + s[n][1];
            rs1 += s[n][2] + s[n][3];
        }
        rs0 += __shfl_xor_sync(0xffffffffu, rs0, 1);
        rs0 += __shfl_xor_sync(0xffffffffu, rs0, 2);
        rs1 += __shfl_xor_sync(0xffffffffu, rs1, 1);
        rs1 += __shfl_xor_sync(0xffffffffu, rs1, 2);
        l0 = l0 * a0 + rs0;
        l1 = l1 * a1 + rs1;
        m0 = mx0; m1 = mx1;
#pragma unroll
        for (int n = 0; n < 8; ++n) {
            o[n][0] *= a0; o[n][1] *= a0; o[n][2] *= a1; o[n][3] *= a1;
        }

        __syncthreads();
        {
            const int pc = ac * 2;
#pragma unroll
            for (int n = 0; n < 8; ++n) {
                KP[ar * KPS + n * 8 + pc]           = __uint_as_float(f2tf32(s[n][0]));
                KP[ar * KPS + n * 8 + pc + 1]       = __uint_as_float(f2tf32(s[n][1]));
                KP[(ar + 8) * KPS + n * 8 + pc]     = __uint_as_float(f2tf32(s[n][2]));
                KP[(ar + 8) * KPS + n * 8 + pc + 1] = __uint_as_float(f2tf32(s[n][3]));
            }
        }
        __syncwarp();

#pragma unroll
        for (int ks = 0; ks < 8; ++ks) {
            uint32_t a[4];
            a[0] = __float_as_uint(KP[ar * KPS + ks * 8 + ac]);
            a[1] = __float_as_uint(KP[(ar + 8) * KPS + ks * 8 + ac]);
            a[2] = __float_as_uint(KP[ar * KPS + ks * 8 + ac + 4]);
            a[3] = __float_as_uint(KP[(ar + 8) * KPS + ks * 8 + ac + 4]);
#pragma unroll
            for (int n = 0; n < 8; ++n) {
                uint32_t bf[2];
                bf[0] = __float_as_uint(Vs[(ks * 8 + ac) * VSS + n * 8 + g]);
                bf[1] = __float_as_uint(Vs[(ks * 8 + ac + 4) * VSS + n * 8 + g]);
                mma_tf32(o[n], a, bf);
            }
        }
    }

    float* op = g_Opart + ((size_t)split * NROWS_C + (size_t)b * S_C + q0) * DK_C;
    const int cb = ac * 2;
#pragma unroll
    for (int n = 0; n < 8; ++n) {
        int col = n * 8 + cb;
        *reinterpret_cast<float2*>(&op[(size_t)ar * DK_C + col]) =
            make_float2(o[n][0], o[n][1]);
        *reinterpret_cast<float2*>(&op[(size_t)(ar + 8) * DK_C + col]) =
            make_float2(o[n][2], o[n][3]);
    }
    if (ac == 0) {
        size_t base = (size_t)split * NROWS_C + (size_t)b * S_C + q0;
        g_m[base + ar] = m0;     g_l[base + ar] = l0;
        g_m[base + ar + 8] = m1; g_l[base + ar + 8] = l1;
    }
}

// ---------------------------------------------------------------------------
// Kernel 3: combine partial results across splits.
// ---------------------------------------------------------------------------
__global__ __launch_bounds__(256)
void combine_kernel(float* __restrict__ out)
{
    int idx = blockIdx.x * 256 + threadIdx.x;   // NROWS_C * 16 total
    int row = idx >> 4;
    int c4  = (idx & 15) * 4;

    float ms[NSPLIT];
    float m = -1e30f;
#pragma unroll
    for (int s = 0; s < NSPLIT; ++s) {
        ms[s] = g_m[(size_t)s * NROWS_C + row];
        m = fmaxf(m, ms[s]);
    }
    float l = 0.f;
    float ox = 0.f, oy = 0.f, oz = 0.f, ow = 0.f;
#pragma unroll
    for (int s = 0; s < NSPLIT; ++s) {
        float w = exp2_approx(ms[s] - m);
        l += g_l[(size_t)s * NROWS_C + row] * w;
        float4 p = *reinterpret_cast<const float4*>(
            &g_Opart[((size_t)s * NROWS_C + row) * DK_C + c4]);
        ox += p.x * w; oy += p.y * w; oz += p.z * w; ow += p.w * w;
    }
    float inv = 1.f / l;
    *reinterpret_cast<float4*>(&out[(size_t)row * DK_C + c4]) =
        make_float4(ox * inv, oy * inv, oz * inv, ow * inv);
}

// ---------------------------------------------------------------------------
extern "C" void kernel_launch(void* const* d_in, const int* in_sizes, int n_in,
                              void* d_out, int out_size) {
    (void)in_sizes; (void)n_in; (void)out_size;
    const float* emb = (const float*)d_in[0];
    const float* Wq  = (const float*)d_in[1];
    const float* bq  = (const float*)d_in[2];
    const float* Wk  = (const float*)d_in[3];
    const float* bk  = (const float*)d_in[4];
    const float* Wv  = (const float*)d_in[5];
    const float* bv  = (const float*)d_in[6];

    dim3 qgrid(NROWS_C / 64, 3);
    qkv_proj_kernel<<<qgrid, 256>>>(emb, Wq, bq, Wk, bk, Wv, bv);
    dim3 agrid(S_C / 64, B_C, NSPLIT);
    attn_kernel<<<agrid, 128>>>();
    combine_kernel<<<(NROWS_C * 16) / 256, 256>>>((float*)d_out);
}

// round 6
// speedup vs baseline: 1.5946x; 1.5946x over previous
#include <cuda_runtime.h>
#include <cstdint>

#define D_MODEL_C 1024
#define DK_C 64
#define B_C 4
#define S_C 4096
#define NROWS_C (B_C * S_C)
#define NSPLIT 4
#define KV_PER_SPLIT (S_C / NSPLIT)          // 1024
#define TILES_PER_SPLIT (KV_PER_SPLIT / 64)  // 16

// Scratch (fp32). Static device arrays: allocation-free.
__device__ float g_Q[NROWS_C * DK_C];
__device__ float g_K[NROWS_C * DK_C];
__device__ float g_V[NROWS_C * DK_C];
__device__ float g_Opart[NSPLIT * NROWS_C * DK_C];   // unnormalized partial O
__device__ float g_m[NSPLIT * NROWS_C];
__device__ float g_l[NSPLIT * NROWS_C];

static __device__ __forceinline__ uint32_t f2tf32(float f) {
    uint32_t u;
    asm("cvt.rna.tf32.f32 %0, %1;" : "=r"(u) : "f"(f));
    return u;
}
static __device__ __forceinline__ float tf32r(float f) {
    return __uint_as_float(f2tf32(f));
}
static __device__ __forceinline__ float exp2_approx(float x) {
    float y;
    asm("ex2.approx.f32 %0, %1;" : "=f"(y) : "f"(x));
    return y;
}
static __device__ __forceinline__ void mma_tf32(float c[4], const uint32_t a[4], const uint32_t b[2]) {
    asm volatile(
        "mma.sync.aligned.m16n8k8.row.col.f32.tf32.tf32.f32 "
        "{%0,%1,%2,%3}, {%4,%5,%6,%7}, {%8,%9}, {%0,%1,%2,%3};\n"
        : "+f"(c[0]), "+f"(c[1]), "+f"(c[2]), "+f"(c[3])
        : "r"(a[0]), "r"(a[1]), "r"(a[2]), "r"(a[3]), "r"(b[0]), "r"(b[1]));
}

// ---------------------------------------------------------------------------
// Kernel 1: QKV projection, single-pass TF32.
// Grid (NROWS/128, 3). Block 256 (8 warps). CTA tile 128x64.
// Warp = (row-slab of 32) x (col-half of 32): 2 m16-tiles x 4 n8-tiles.
// B-fragments shared across both m-tiles -> 2 LDS per MMA.
// ---------------------------------------------------------------------------
#define QKC 32      // K-chunk
#define QES_S 36    // emb stride: 36 mod 32 = 4 -> a-frag banks 4g+ac distinct
#define QWS_S 72    // W stride:   72 mod 32 = 8 -> b-frag banks 8ac+g distinct

__global__ __launch_bounds__(256)
void qkv_proj_kernel(const float* __restrict__ emb,
                     const float* __restrict__ Wq, const float* __restrict__ bq,
                     const float* __restrict__ Wk, const float* __restrict__ bk,
                     const float* __restrict__ Wv, const float* __restrict__ bv)
{
    __shared__ float Es[128 * QES_S];   // emb tile 128x32 (tf32-rounded), 18 KB
    __shared__ float Ws[QKC * QWS_S];   // W tile 32x64 (tf32-rounded), 9.2 KB

    const int tid  = threadIdx.x;
    const int warp = tid >> 5;
    const int lane = tid & 31;
    const int rs   = warp & 3;      // row slab (32 rows)
    const int ch   = warp >> 2;     // col half (32 cols)
    const int row0 = blockIdx.x * 128;
    const int mat  = blockIdx.y;

    const float* W    = (mat == 0) ? Wq : (mat == 1) ? Wk : Wv;
    const float* bias = (mat == 0) ? bq : (mat == 1) ? bk : bv;
    float* outp       = (mat == 0) ? g_Q : (mat == 1) ? g_K : g_V;

    float acc[2][4][4];
#pragma unroll
    for (int mt = 0; mt < 2; ++mt)
#pragma unroll
        for (int n = 0; n < 4; ++n)
#pragma unroll
            for (int j = 0; j < 4; ++j) acc[mt][n][j] = 0.f;

    const int g  = lane >> 2;
    const int ac = lane & 3;

    // writer indices (constant across kc)
    const int er  = tid >> 3;            // emb row 0..31 (+i*32)
    const int ec4 = (tid & 7) * 4;       // emb col 0..28
    const int wr  = tid >> 4;            // W row 0..15 (+i*16)
    const int wc4 = (tid & 15) * 4;      // W col 0..60

    for (int kc = 0; kc < D_MODEL_C / QKC; ++kc) {
        __syncthreads();
        // emb tile 128x32: 1024 float4, 4 per thread
#pragma unroll
        for (int i = 0; i < 4; ++i) {
            int r = er + i * 32;
            float4 v = *reinterpret_cast<const float4*>(
                &emb[(size_t)(row0 + r) * D_MODEL_C + kc * QKC + ec4]);
            *reinterpret_cast<float4*>(&Es[r * QES_S + ec4]) =
                make_float4(tf32r(v.x), tf32r(v.y), tf32r(v.z), tf32r(v.w));
        }
        // W tile 32x64: 512 float4, 2 per thread
#pragma unroll
        for (int i = 0; i < 2; ++i) {
            int r = wr + i * 16;
            float4 v = *reinterpret_cast<const float4*>(
                &W[(size_t)(kc * QKC + r) * DK_C + wc4]);
            *reinterpret_cast<float4*>(&Ws[r * QWS_S + wc4]) =
                make_float4(tf32r(v.x), tf32r(v.y), tf32r(v.z), tf32r(v.w));
        }
        __syncthreads();
#pragma unroll
        for (int ks = 0; ks < QKC / 8; ++ks) {
            uint32_t a[2][4];
#pragma unroll
            for (int mt = 0; mt < 2; ++mt) {
                const int r0 = rs * 32 + mt * 16 + g;
                a[mt][0] = __float_as_uint(Es[r0 * QES_S + ks * 8 + ac]);
                a[mt][1] = __float_as_uint(Es[(r0 + 8) * QES_S + ks * 8 + ac]);
                a[mt][2] = __float_as_uint(Es[r0 * QES_S + ks * 8 + ac + 4]);
                a[mt][3] = __float_as_uint(Es[(r0 + 8) * QES_S + ks * 8 + ac + 4]);
            }
            const int brow = ks * 8 + ac;
#pragma unroll
            for (int n = 0; n < 4; ++n) {
                const int bcol = ch * 32 + n * 8 + g;
                uint32_t b[2];
                b[0] = __float_as_uint(Ws[brow * QWS_S + bcol]);
                b[1] = __float_as_uint(Ws[(brow + 4) * QWS_S + bcol]);
                mma_tf32(acc[0][n], a[0], b);
                mma_tf32(acc[1][n], a[1], b);
            }
        }
    }
    // Epilogue: bias add, fp32 stores
    const int cb = ac * 2;
#pragma unroll
    for (int mt = 0; mt < 2; ++mt) {
        const int r = row0 + rs * 32 + mt * 16 + g;
#pragma unroll
        for (int n = 0; n < 4; ++n) {
            int col = ch * 32 + n * 8 + cb;
            float b0 = bias[col], b1 = bias[col + 1];
            *reinterpret_cast<float2*>(&outp[(size_t)r * DK_C + col]) =
                make_float2(acc[mt][n][0] + b0, acc[mt][n][1] + b1);
            *reinterpret_cast<float2*>(&outp[(size_t)(r + 8) * DK_C + col]) =
                make_float2(acc[mt][n][2] + b0, acc[mt][n][3] + b1);
        }
    }
}

// ---------------------------------------------------------------------------
// Kernel 2: flash attention, split-KV (4 splits). Br=Bc=64, 4 warps.
// (unchanged — frozen to isolate qkv delta)
// ---------------------------------------------------------------------------
#define KPS 68
#define VSS 72

__global__ __launch_bounds__(128)
void attn_kernel()
{
    __shared__ float KP[64 * KPS];   // Q staging, then K tile, then P tile
    __shared__ float Vs[64 * VSS];   // V tile

    const int tid   = threadIdx.x;
    const int warp  = tid >> 5;
    const int lane  = tid & 31;
    const int b     = blockIdx.y;
    const int q0    = blockIdx.x * 64;
    const int split = blockIdx.z;
    const int t0    = split * TILES_PER_SPLIT;

    const float* Qg = g_Q + ((size_t)b * S_C + q0) * DK_C;
    const float* Kg = g_K + (size_t)b * S_C * DK_C;
    const float* Vg = g_V + (size_t)b * S_C * DK_C;

#pragma unroll
    for (int i = 0; i < 8; ++i) {
        int id = tid + i * 128;
        int r = id >> 4, c4 = (id & 15) * 4;
        *reinterpret_cast<float4*>(&KP[r * KPS + c4]) =
            *reinterpret_cast<const float4*>(&Qg[(size_t)r * DK_C + c4]);
    }
    __syncthreads();

    const int ar = warp * 16 + (lane >> 2);
    const int ac = lane & 3;
    const int g  = lane >> 2;
    const float qsc = 1.4426950408889634f * 0.125f;  // log2(e)/sqrt(dk)
    uint32_t qf[8][4];
#pragma unroll
    for (int ks = 0; ks < 8; ++ks) {
        qf[ks][0] = f2tf32(KP[ar * KPS + ks * 8 + ac] * qsc);
        qf[ks][1] = f2tf32(KP[(ar + 8) * KPS + ks * 8 + ac] * qsc);
        qf[ks][2] = f2tf32(KP[ar * KPS + ks * 8 + ac + 4] * qsc);
        qf[ks][3] = f2tf32(KP[(ar + 8) * KPS + ks * 8 + ac + 4] * qsc);
    }

    float o[8][4];
#pragma unroll
    for (int n = 0; n < 8; ++n)
#pragma unroll
        for (int j = 0; j < 4; ++j) o[n][j] = 0.f;
    float m0 = -1e30f, m1 = -1e30f, l0 = 0.f, l1 = 0.f;

    for (int tt = 0; tt < TILES_PER_SPLIT; ++tt) {
        const int t = t0 + tt;
        __syncthreads();
        const float* Kt = Kg + (size_t)t * 64 * DK_C;
        const float* Vt = Vg + (size_t)t * 64 * DK_C;
#pragma unroll
        for (int i = 0; i < 8; ++i) {
            int id = tid + i * 128;
            int r = id >> 4, c4 = (id & 15) * 4;
            float4 kv = *reinterpret_cast<const float4*>(&Kt[(size_t)r * DK_C + c4]);
            float4 vv = *reinterpret_cast<const float4*>(&Vt[(size_t)r * DK_C + c4]);
            float* kd = &KP[r * KPS + c4];
            float* vd = &Vs[r * VSS + c4];
            kd[0] = tf32r(kv.x);
            kd[1] = tf32r(kv.y);
            kd[2] = tf32r(kv.z);
            kd[3] = tf32r(kv.w);
            vd[0] = tf32r(vv.x);
            vd[1] = tf32r(vv.y);
            vd[2] = tf32r(vv.z);
            vd[3] = tf32r(vv.w);
        }
        __syncthreads();

        float s[8][4];
#pragma unroll
        for (int n = 0; n < 8; ++n)
#pragma unroll
            for (int j = 0; j < 4; ++j) s[n][j] = 0.f;
#pragma unroll
        for (int ks = 0; ks < 8; ++ks) {
#pragma unroll
            for (int n = 0; n < 8; ++n) {
                uint32_t bf[2];
                bf[0] = __float_as_uint(KP[(n * 8 + g) * KPS + ks * 8 + ac]);
                bf[1] = __float_as_uint(KP[(n * 8 + g) * KPS + ks * 8 + ac + 4]);
                mma_tf32(s[n], qf[ks], bf);
            }
        }

        float mx0 = m0, mx1 = m1;
#pragma unroll
        for (int n = 0; n < 8; ++n) {
            mx0 = fmaxf(mx0, fmaxf(s[n][0], s[n][1]));
            mx1 = fmaxf(mx1, fmaxf(s[n][2], s[n][3]));
        }
        mx0 = fmaxf(mx0, __shfl_xor_sync(0xffffffffu, mx0, 1));
        mx0 = fmaxf(mx0, __shfl_xor_sync(0xffffffffu, mx0, 2));
        mx1 = fmaxf(mx1, __shfl_xor_sync(0xffffffffu, mx1, 1));
        mx1 = fmaxf(mx1, __shfl_xor_sync(0xffffffffu, mx1, 2));
        float a0 = exp2_approx(m0 - mx0);
        float a1 = exp2_approx(m1 - mx1);
        float rs0 = 0.f, rs1 = 0.f;
#pragma unroll
        for (int n = 0; n < 8; ++n) {
            s[n][0] = exp2_approx(s[n][0] - mx0);
            s[n][1] = exp2_approx(s[n][1] - mx0);
            s[n][2] = exp2_approx(s[n][2] - mx1);
            s[n][3] = exp2_approx(s[n][3] - mx1);
            rs0 += s[n][0] + s[n][1];
            rs1 += s[n][2] + s[n][3];
        }
        rs0 += __shfl_xor_sync(0xffffffffu, rs0, 1);
        rs0 += __shfl_xor_sync(0xffffffffu, rs0, 2);
        rs1 += __shfl_xor_sync(0xffffffffu, rs1, 1);
        rs1 += __shfl_xor_sync(0xffffffffu, rs1, 2);
        l0 = l0 * a0 + rs0;
        l1 = l1 * a1 + rs1;
        m0 = mx0; m1 = mx1;
#pragma unroll
        for (int n = 0; n < 8; ++n) {
            o[n][0] *= a0; o[n][1] *= a0; o[n][2] *= a1; o[n][3] *= a1;
        }

        __syncthreads();
        {
            const int pc = ac * 2;
#pragma unroll
            for (int n = 0; n < 8; ++n) {
                KP[ar * KPS + n * 8 + pc]           = tf32r(s[n][0]);
                KP[ar * KPS + n * 8 + pc + 1]       = tf32r(s[n][1]);
                KP[(ar + 8) * KPS + n * 8 + pc]     = tf32r(s[n][2]);
                KP[(ar + 8) * KPS + n * 8 + pc + 1] = tf32r(s[n][3]);
            }
        }
        __syncwarp();

#pragma unroll
        for (int ks = 0; ks < 8; ++ks) {
            uint32_t a[4];
            a[0] = __float_as_uint(KP[ar * KPS + ks * 8 + ac]);
            a[1] = __float_as_uint(KP[(ar + 8) * KPS + ks * 8 + ac]);
            a[2] = __float_as_uint(KP[ar * KPS + ks * 8 + ac + 4]);
            a[3] = __float_as_uint(KP[(ar + 8) * KPS + ks * 8 + ac + 4]);
#pragma unroll
            for (int n = 0; n < 8; ++n) {
                uint32_t bf[2];
                bf[0] = __float_as_uint(Vs[(ks * 8 + ac) * VSS + n * 8 + g]);
                bf[1] = __float_as_uint(Vs[(ks * 8 + ac + 4) * VSS + n * 8 + g]);
                mma_tf32(o[n], a, bf);
            }
        }
    }

    float* op = g_Opart + ((size_t)split * NROWS_C + (size_t)b * S_C + q0) * DK_C;
    const int cb = ac * 2;
#pragma unroll
    for (int n = 0; n < 8; ++n) {
        int col = n * 8 + cb;
        *reinterpret_cast<float2*>(&op[(size_t)ar * DK_C + col]) =
            make_float2(o[n][0], o[n][1]);
        *reinterpret_cast<float2*>(&op[(size_t)(ar + 8) * DK_C + col]) =
            make_float2(o[n][2], o[n][3]);
    }
    if (ac == 0) {
        size_t base = (size_t)split * NROWS_C + (size_t)b * S_C + q0;
        g_m[base + ar] = m0;     g_l[base + ar] = l0;
        g_m[base + ar + 8] = m1; g_l[base + ar + 8] = l1;
    }
}

// ---------------------------------------------------------------------------
// Kernel 3: combine partial results across splits.
// ---------------------------------------------------------------------------
__global__ __launch_bounds__(256)
void combine_kernel(float* __restrict__ out)
{
    int idx = blockIdx.x * 256 + threadIdx.x;   // NROWS_C * 16 total
    int row = idx >> 4;
    int c4  = (idx & 15) * 4;

    float ms[NSPLIT];
    float m = -1e30f;
#pragma unroll
    for (int s = 0; s < NSPLIT; ++s) {
        ms[s] = g_m[(size_t)s * NROWS_C + row];
        m = fmaxf(m, ms[s]);
    }
    float l = 0.f;
    float ox = 0.f, oy = 0.f, oz = 0.f, ow = 0.f;
#pragma unroll
    for (int s = 0; s < NSPLIT; ++s) {
        float w = exp2_approx(ms[s] - m);
        l += g_l[(size_t)s * NROWS_C + row] * w;
        float4 p = *reinterpret_cast<const float4*>(
            &g_Opart[((size_t)s * NROWS_C + row) * DK_C + c4]);
        ox += p.x * w; oy += p.y * w; oz += p.z * w; ow += p.w * w;
    }
    float inv = 1.f / l;
    *reinterpret_cast<float4*>(&out[(size_t)row * DK_C + c4]) =
        make_float4(ox * inv, oy * inv, oz * inv, ow * inv);
}

// ---------------------------------------------------------------------------
extern "C" void kernel_launch(void* const* d_in, const int* in_sizes, int n_in,
                              void* d_out, int out_size) {
    (void)in_sizes; (void)n_in; (void)out_size;
    const float* emb = (const float*)d_in[0];
    const float* Wq  = (const float*)d_in[1];
    const float* bq  = (const float*)d_in[2];
    const float* Wk  = (const float*)d_in[3];
    const float* bk  = (const float*)d_in[4];
    const float* Wv  = (const float*)d_in[5];
    const float* bv  = (const float*)d_in[6];

    dim3 qgrid(NROWS_C / 128, 3);
    qkv_proj_kernel<<<qgrid, 256>>>(emb, Wq, bq, Wk, bk, Wv, bv);
    dim3 agrid(S_C / 64, B_C, NSPLIT);
    attn_kernel<<<agrid, 128>>>();
    combine_kernel<<<(NROWS_C * 16) / 256, 256>>>((float*)d_out);
}